// round 11
// baseline (speedup 1.0000x reference)
#include <cuda_runtime.h>
#include <cstdint>

#define B 2
#define N 2048
#define C 768
#define CG 192                       // C/4 float4 groups
#define NCH 256                      // chunk CTAs (X work)
#define NRED 32                      // reducer CTAs (s->u->v pipeline)
#define G (NCH + NRED)               // 288 total, 2/SM co-resident (<=296)
#define T 256
#define ROWS_PER 16                  // X rows per chunk CTA
#define XCHUNK_BYTES (ROWS_PER * C * 4)     // 49152
#define JPER 24                      // j rows per reducer (32*24 = 768)
#define WK_BYTES (JPER * C * 4)             // 73728
#define SH_OFF WK_BYTES                     // sh after larger of xbuf/wkbuf
#define SMEM_BYTES (SH_OFF + 2 * CG * 16)   // 79872

__device__ float4 g_part[B][128][CG];   // P1: partial colsums
__device__ float  g_s[B][C];
__device__ float4 g_vpart[B][NRED][CG];
__device__ float  g_v[B][C];

// Each counter on its own 128B line; monotonic => replay-safe without reset.
struct __align__(128) Cnt { unsigned v; unsigned pad[31]; };
__device__ Cnt g_bar0;                  // all-CTA arrival (288/launch)
__device__ Cnt g_rbar[2];               // reducer-only syncs (32/launch each)
__device__ Cnt g_flag;                  // v-ready (32 bumps/launch)

__device__ __forceinline__ float4 f4add(float4 a, float4 b) {
    return make_float4(a.x + b.x, a.y + b.y, a.z + b.z, a.w + b.w);
}
__device__ __forceinline__ float4 f4fma(float4 a, float s, float4 acc) {
    return make_float4(fmaf(a.x, s, acc.x), fmaf(a.y, s, acc.y),
                       fmaf(a.z, s, acc.z), fmaf(a.w, s, acc.w));
}
__device__ __forceinline__ uint32_t smem_u32(const void* p) {
    uint32_t a;
    asm("{ .reg .u64 t; cvta.to.shared.u64 t, %1; cvt.u32.u64 %0, t; }"
        : "=r"(a) : "l"(p));
    return a;
}
__device__ __forceinline__ void mbar_wait(uint32_t mbar, uint32_t parity) {
    asm volatile(
        "{\n\t.reg .pred P;\n"
        "W_%=:\n\t"
        "mbarrier.try_wait.parity.shared.b64 P, [%0], %1;\n\t"
        "@!P bra W_%=;\n\t}"
        :: "r"(mbar), "r"(parity) : "memory");
}

// Reducer-internal barrier: 32 arrivals per launch, monotonic target.
__device__ __forceinline__ void red_sync(int i) {
    __threadfence();
    __syncthreads();
    if (threadIdx.x == 0) {
        unsigned old = atomicAdd(&g_rbar[i].v, 1u);
        unsigned target = (old / NRED + 1u) * NRED;
        volatile unsigned* p = &g_rbar[i].v;
        while (*p < target) { }
        __threadfence();
    }
    __syncthreads();
}

extern __shared__ char smem_raw[];

__global__ void __launch_bounds__(T, 2)
fused_att_scores(const float4* __restrict__ X4, const float4* __restrict__ W4,
                 float* __restrict__ out) {
    float4* buf = (float4*)smem_raw;               // xbuf (48K) or wkbuf (72K)
    float4* sh  = (float4*)(smem_raw + SH_OFF);    // 6 KB staging
    __shared__ uint64_t mbar_st;
    __shared__ float u0s[JPER], u1s[JPER];
    const uint32_t mb = smem_u32(&mbar_st);
    const int ct  = blockIdx.x;
    const int tid = threadIdx.x;
    const bool red = (ct < NRED);

    // Flag baseline: read BEFORE this CTA's bar0 arrival (flag can only bump
    // after all 288 arrive, so this read is race-free).
    unsigned fbase = 0;
    if (tid == 0) fbase = *(volatile unsigned*)&g_flag.v;

    if (!red) {
        // ===================== CHUNK CTA =====================
        const int cid = ct - NRED;
        const int b = cid & 1, chunk = cid >> 1;   // 128 chunks per batch
        const char* xsrc =
            (const char*)(X4 + ((size_t)b * N + chunk * ROWS_PER) * CG);

        if (tid == 0) {
            asm volatile("mbarrier.init.shared.b64 [%0], 1;" :: "r"(mb) : "memory");
            asm volatile("fence.proxy.async.shared::cta;" ::: "memory");
            asm volatile("mbarrier.arrive.expect_tx.shared.b64 _, [%0], %1;"
                         :: "r"(mb), "r"((uint32_t)XCHUNK_BYTES) : "memory");
            asm volatile(
                "cp.async.bulk.shared::cta.global.mbarrier::complete_tx::bytes "
                "[%0], [%1], %2, [%3];"
                :: "r"(smem_u32(buf)), "l"(xsrc),
                   "r"((uint32_t)XCHUNK_BYTES), "r"(mb) : "memory");
        }
        __syncthreads();
        mbar_wait(mb, 0);

        // P1: reduce 16 rows -> g_part
        if (tid < CG) {
            float4 a0 = make_float4(0.f, 0.f, 0.f, 0.f), a1 = a0;
#pragma unroll
            for (int r = 0; r < ROWS_PER; r += 2) {
                a0 = f4add(a0, buf[r * CG + tid]);
                a1 = f4add(a1, buf[(r + 1) * CG + tid]);
            }
            g_part[b][chunk][tid] = f4add(a0, a1);
        }
        // arrive bar0 (never wait on it)
        __threadfence();
        __syncthreads();
        if (tid == 0) {
            atomicAdd(&g_bar0.v, 1u);
            // wait for v: 32 flag bumps this launch
            volatile unsigned* fp = &g_flag.v;
            while (*fp < fbase + NRED) { }
            __threadfence();
        }
        __syncthreads();

        // P5: scores from retained smem X
        if (tid < CG) sh[tid] = ((const float4*)g_v[b])[tid];
        __syncthreads();
        int wid = tid >> 5, lane = tid & 31;
        int nbase = chunk * ROWS_PER + wid * 2;
        float a[2];
#pragma unroll
        for (int r = 0; r < 2; ++r) {
            const float4* x = buf + (wid * 2 + r) * CG;
            float acc = 0.f;
#pragma unroll
            for (int k = 0; k < 6; ++k) {
                int c4 = lane + k * 32;
                float4 xv = x[c4];
                float4 vv = sh[c4];
                acc += xv.x * vv.x + xv.y * vv.y + xv.z * vv.z + xv.w * vv.w;
            }
            a[r] = acc;
        }
#pragma unroll
        for (int o = 16; o > 0; o >>= 1) {
#pragma unroll
            for (int r = 0; r < 2; ++r)
                a[r] += __shfl_down_sync(0xFFFFFFFFu, a[r], o);
        }
        if (lane == 0) {
#pragma unroll
            for (int r = 0; r < 2; ++r)
                out[b * N + nbase + r] = 0.125f * a[r];
        }
        return;
    }

    // ===================== REDUCER CTA =====================
    const int j0 = ct * JPER;
    const char* wksrc = (const char*)(W4 + (size_t)(C + j0) * CG);  // Wk rows
    const char* wqsrc = (const char*)(W4 + (size_t)j0 * CG);        // Wq rows

    // t=0: TMA Wk rows into smem; prefetch Wq rows into L2.
    if (tid == 0) {
        asm volatile("mbarrier.init.shared.b64 [%0], 1;" :: "r"(mb) : "memory");
        asm volatile("fence.proxy.async.shared::cta;" ::: "memory");
        asm volatile("mbarrier.arrive.expect_tx.shared.b64 _, [%0], %1;"
                     :: "r"(mb), "r"((uint32_t)WK_BYTES) : "memory");
        asm volatile(
            "cp.async.bulk.shared::cta.global.mbarrier::complete_tx::bytes "
            "[%0], [%1], %2, [%3];"
            :: "r"(smem_u32(buf)), "l"(wksrc),
               "r"((uint32_t)WK_BYTES), "r"(mb) : "memory");
    }
    for (int i = tid; i < WK_BYTES / 128; i += T)
        asm volatile("prefetch.global.L2 [%0];" :: "l"(wqsrc + i * 128));
    __syncthreads();

    // bar0: arrive + wait for all 288 (chunk partials done).
    __threadfence();
    __syncthreads();
    if (tid == 0) {
        unsigned old = atomicAdd(&g_bar0.v, 1u);
        unsigned target = (old / G + 1u) * G;
        volatile unsigned* p = &g_bar0.v;
        while (*p < target) { }
        __threadfence();
    }
    __syncthreads();

    // P2: reduce 128 partials -> s slice (48 floats for batch bb).
    {
        int bb = ct & 1, qs = ct >> 1;             // qs in [0,16)
        int base = qs * 12;
        if (tid < 192) {
            int gi = tid % 12, sl = tid / 12;      // 16 slices x 8 partials
            float4 acc = make_float4(0.f, 0.f, 0.f, 0.f);
#pragma unroll
            for (int k = 0; k < 8; ++k)
                acc = f4add(acc, g_part[bb][sl * 8 + k][base + gi]);
            sh[tid] = acc;
        }
        __syncthreads();
        if (tid < 12) {
            float4 v = make_float4(0.f, 0.f, 0.f, 0.f);
#pragma unroll
            for (int s = 0; s < 16; ++s)
                v = f4add(v, sh[s * 12 + tid]);
            ((float4*)g_s[bb])[base + tid] = v;
        }
    }
    red_sync(0);

    // u_j = Wk_j . s (Wk from smem), then vpart = sum_j u_j * Wq_j (Wq L2-hot).
    {
        for (int i = tid; i < 2 * CG; i += T)      // stage s (both batches)
            sh[i] = (i < CG) ? ((const float4*)g_s[0])[i]
                             : ((const float4*)g_s[1])[i - CG];
        mbar_wait(mb, 0);                          // Wk TMA (done long ago)
        __syncthreads();
        int wid = tid >> 5, lane = tid & 31;
#pragma unroll
        for (int r = 0; r < 3; ++r) {              // 8 warps x 3 rows = 24
            int jj = wid * 3 + r;
            const float4* row = buf + jj * CG;
            float a0 = 0.f, a1 = 0.f;
#pragma unroll
            for (int k = 0; k < 6; ++k) {
                int c4 = lane + k * 32;
                float4 w  = row[c4];
                float4 v0 = sh[c4];
                float4 v1 = sh[CG + c4];
                a0 += w.x * v0.x + w.y * v0.y + w.z * v0.z + w.w * v0.w;
                a1 += w.x * v1.x + w.y * v1.y + w.z * v1.z + w.w * v1.w;
            }
#pragma unroll
            for (int o = 16; o > 0; o >>= 1) {
                a0 += __shfl_down_sync(0xFFFFFFFFu, a0, o);
                a1 += __shfl_down_sync(0xFFFFFFFFu, a1, o);
            }
            if (lane == 0) { u0s[jj] = a0; u1s[jj] = a1; }
        }
        __syncthreads();
        if (tid < CG) {
            float4 a0 = make_float4(0.f, 0.f, 0.f, 0.f);
            float4 a1 = make_float4(0.f, 0.f, 0.f, 0.f);
#pragma unroll
            for (int jj = 0; jj < JPER; ++jj) {
                float4 w = W4[(size_t)(j0 + jj) * CG + tid];   // Wq (L2)
                a0 = f4fma(w, u0s[jj], a0);
                a1 = f4fma(w, u1s[jj], a1);
            }
            g_vpart[0][ct][tid] = a0;
            g_vpart[1][ct][tid] = a1;
        }
    }
    red_sync(1);

    // P4: reduce 32 vparts -> v slice, then bump flag (32 bumps total).
    {
        int bb = ct & 1, qs = ct >> 1;
        int base = qs * 12;
        if (tid < 192) {
            int gi = tid % 12, sl = tid / 12;      // 16 slices x 2 partials
            float4 acc = f4add(g_vpart[bb][sl * 2][base + gi],
                               g_vpart[bb][sl * 2 + 1][base + gi]);
            sh[tid] = acc;
        }
        __syncthreads();
        if (tid < 12) {
            float4 v = make_float4(0.f, 0.f, 0.f, 0.f);
#pragma unroll
            for (int s = 0; s < 16; ++s)
                v = f4add(v, sh[s * 12 + tid]);
            ((float4*)g_v[bb])[base + tid] = v;
        }
    }
    __threadfence();
    __syncthreads();
    if (tid == 0)
        atomicAdd(&g_flag.v, 1u);                  // release: v slice visible
}

extern "C" void kernel_launch(void* const* d_in, const int* in_sizes, int n_in,
                              void* d_out, int out_size) {
    const float4* X4 = (const float4*)d_in[0];  // [2, 2048, 768] f32
    const float4* W4 = (const float4*)d_in[1];  // [1536, 768] f32
    float* out = (float*)d_out;                 // [2, 2048] f32
    (void)in_sizes; (void)n_in; (void)out_size;

    cudaFuncSetAttribute(fused_att_scores,
                         cudaFuncAttributeMaxDynamicSharedMemorySize, SMEM_BYTES);
    fused_att_scores<<<G, T, SMEM_BYTES>>>(X4, W4, out);
}